// round 16
// baseline (speedup 1.0000x reference)
#include <cuda_runtime.h>
#include <cuda_bf16.h>

#define NVOX 524288
#define VOXB 262144

__device__ __nv_bfloat16 g_y[27 * NVOX];
__device__ __align__(16) __nv_bfloat16 g_feabf[8192 * 64];
__device__ __align__(16) __nv_bfloat16 g_w72[192 * 72];      // [few|qw] padded, Bs layout
__device__ __align__(16) __nv_bfloat16 g_dwc104[32 * 104];   // dwc_w, conv1A Bs layout
__device__ __align__(16) __nv_bfloat16 g_upc40[96 * 40];     // upc_w, conv2 Bs layout
__device__ __align__(16) __nv_bfloat16 g_fea2bf[8192 * 128];
__device__ __align__(16) __nv_bfloat16 g_cwbf[1024 * 128];
__device__ float g_q[8192 * 64];
__device__ float g_ga[65536];
__device__ __nv_bfloat16 g_act[8192 * 1024];
__device__ float g_csum[1024];
__device__ float g_csumsq[1024];
__device__ float g_cent[2 * 128 * 16];
__device__ float g_kT[2 * 64 * 128];
__device__ float g_v[2 * 128 * 64];
__device__ float g_newo[NVOX];

__device__ __forceinline__ void mma_bf16(float c[4], const unsigned a[4], const unsigned b[2]) {
    asm volatile(
        "mma.sync.aligned.m16n8k16.row.col.f32.bf16.bf16.f32 "
        "{%0,%1,%2,%3}, {%4,%5,%6,%7}, {%8,%9}, {%0,%1,%2,%3};"
        : "+f"(c[0]), "+f"(c[1]), "+f"(c[2]), "+f"(c[3])
        : "r"(a[0]), "r"(a[1]), "r"(a[2]), "r"(a[3]), "r"(b[0]), "r"(b[1]));
}

__device__ __forceinline__ unsigned pack_bf16(float lo, float hi) {
    __nv_bfloat162 h = __floats2bfloat162_rn(lo, hi);
    return *(unsigned*)&h;
}

__device__ __forceinline__ void cp16(void* dst, const void* src) {
    unsigned d = (unsigned)__cvta_generic_to_shared(dst);
    asm volatile("cp.async.ca.shared.global [%0], [%1], 16;" :: "r"(d), "l"(src));
}
#define CP_COMMIT() asm volatile("cp.async.commit_group;")
#define CP_WAIT1()  asm volatile("cp.async.wait_group 1;")
#define CP_WAIT0()  asm volatile("cp.async.wait_group 0;")

// ============ P: merged prelude ==================================================
__global__ void k_prelude(const float* __restrict__ cw, const float* __restrict__ few,
                          const float* __restrict__ qw, const float* __restrict__ dwcw,
                          const float* __restrict__ upcw) {
    if (blockIdx.x == 0) {
        int t = threadIdx.x;
        for (int i = t; i < 1024; i += 256) { g_csum[i] = 0.f; g_csumsq[i] = 0.f; }
        for (int i = t; i < 4096; i += 256) g_cent[i] = 0.f;
        for (int i = t; i < 32 * 104; i += 256) {
            int j = i / 104, c = i % 104;
            g_dwc104[i] = __float2bfloat16((j < 27 && c < 96) ? dwcw[c * 27 + j] : 0.f);
        }
        for (int i = t; i < 96 * 40; i += 256) {
            int c = i / 40, j = i % 40;
            g_upc40[i] = __float2bfloat16(j < 27 ? upcw[c * 27 + j] : 0.f);
        }
        return;
    }
    if (blockIdx.x >= 129) {
        int n0 = (blockIdx.x - 129) * 32;
        for (int i = threadIdx.x; i < 32 * 72; i += 256) {
            int n = n0 + i / 72, k = i % 72;
            float v = 0.f;
            if (k < 64) v = (n < 128) ? few[k * 128 + n] : qw[k * 64 + (n - 128)];
            g_w72[n * 72 + (i % 72)] = __float2bfloat16(v);
        }
        return;
    }
    __shared__ float s[32][33];
    int bx = blockIdx.x - 1;
    int n0 = (bx & 31) * 32, k0 = (bx >> 5) * 32;
    int lane = threadIdx.x & 31, wr = threadIdx.x >> 5;
#pragma unroll
    for (int i = 0; i < 4; i++) {
        int k = k0 + wr + i * 8;
        s[wr + i * 8][lane] = cw[(size_t)k * 1024 + n0 + lane];
    }
    __syncthreads();
#pragma unroll
    for (int i = 0; i < 4; i++) {
        int n = n0 + wr + i * 8;
        g_cwbf[(size_t)n * 128 + k0 + lane] = __float2bfloat16(s[lane][wr + i * 8]);
    }
}

// ============ K1: conv1 stage A via bf16 MMA =====================================
__global__ void k_conv1A(const float* __restrict__ x) {
    const int SA = 104;
    __shared__ __align__(16) __nv_bfloat16 As[128 * 104];
    __shared__ __align__(16) __nv_bfloat16 Bs[32 * 104];
    int tid = threadIdx.x, w = tid >> 5, lane = tid & 31;
    int r = lane >> 2, qp = lane & 3;
    int v0 = blockIdx.x * 128;
    // B via cp.async from pre-converted buffer (32 rows x 13 chunks = 416)
    for (int t2 = tid; t2 < 416; t2 += 256) {
        int row = t2 / 13, seg = t2 % 13;
        cp16(&Bs[row * SA + seg * 8], g_dwc104 + row * 104 + seg * 8);
    }
    CP_COMMIT();
#pragma unroll
    for (int it = 0; it < 12; it++) {
        int idx = it * 256 + tid;
        int row = idx / 24, p = idx % 24;
        float4 f = *(const float4*)(x + (size_t)(v0 + row) * 96 + 4 * p);
        uint2 u = make_uint2(pack_bf16(f.x, f.y), pack_bf16(f.z, f.w));
        *(uint2*)&As[row * SA + 4 * p] = u;
    }
    CP_WAIT0();
    __syncthreads();
    int wm = (w & 3) * 32, wn = (w >> 2) * 16;
    float c[2][2][4];
#pragma unroll
    for (int ms = 0; ms < 2; ms++)
#pragma unroll
        for (int ns = 0; ns < 2; ns++)
#pragma unroll
            for (int i = 0; i < 4; i++) c[ms][ns][i] = 0.f;
#pragma unroll
    for (int ks = 0; ks < 6; ks++) {
        int k0 = ks * 16 + 2 * qp;
        unsigned a[2][4], b[2][2];
#pragma unroll
        for (int ms = 0; ms < 2; ms++) {
            int row = wm + ms * 16 + r;
            a[ms][0] = *(unsigned*)&As[row * SA + k0];
            a[ms][1] = *(unsigned*)&As[(row + 8) * SA + k0];
            a[ms][2] = *(unsigned*)&As[row * SA + k0 + 8];
            a[ms][3] = *(unsigned*)&As[(row + 8) * SA + k0 + 8];
        }
#pragma unroll
        for (int ns = 0; ns < 2; ns++) {
            int n = wn + ns * 8 + r;
            b[ns][0] = *(unsigned*)&Bs[n * SA + k0];
            b[ns][1] = *(unsigned*)&Bs[n * SA + k0 + 8];
        }
#pragma unroll
        for (int ms = 0; ms < 2; ms++)
#pragma unroll
            for (int ns = 0; ns < 2; ns++) mma_bf16(c[ms][ns], a[ms], b[ns]);
    }
#pragma unroll
    for (int ms = 0; ms < 2; ms++)
#pragma unroll
        for (int ns = 0; ns < 2; ns++) {
            int v = v0 + wm + ms * 16 + r;
            int j0 = wn + ns * 8 + 2 * qp;
            if (j0 < 27) {
                g_y[j0 * NVOX + v] = __float2bfloat16(c[ms][ns][0]);
                g_y[j0 * NVOX + v + 8] = __float2bfloat16(c[ms][ns][2]);
            }
            if (j0 + 1 < 27) {
                g_y[(j0 + 1) * NVOX + v] = __float2bfloat16(c[ms][ns][1]);
                g_y[(j0 + 1) * NVOX + v + 8] = __float2bfloat16(c[ms][ns][3]);
            }
        }
}

// ============ K2: gather 27 shifted taps + bias -> feabf (b,4096,64) =============
__global__ void k_conv1B(const float* __restrict__ dwc_b) {
    int t = blockIdx.x * 256 + threadIdx.x;
    int b = t >> 18;
    int vox = t & (VOXB - 1);
    int d = vox >> 12, h = (vox >> 6) & 63, w = vox & 63;
    float s = dwc_b[0];
#pragma unroll
    for (int kd = 0; kd < 3; kd++)
#pragma unroll
        for (int kh = 0; kh < 3; kh++)
#pragma unroll
            for (int kw = 0; kw < 3; kw++) {
                int dd = d + kd - 1, hh = h + kh - 1, ww = w + kw - 1;
                if ((unsigned)dd < 64u && (unsigned)hh < 64u && (unsigned)ww < 64u)
                    s += __bfloat162float(g_y[(kd * 9 + kh * 3 + kw) * NVOX + b * VOXB + (dd << 12) + (hh << 6) + ww]);
            }
    int n = ((d >> 2) << 8) + ((h >> 2) << 4) + (w >> 2);
    int f = ((d & 3) << 4) + ((h & 3) << 2) + (w & 3);
    g_feabf[((b << 12) + n) * 64 + f] = __float2bfloat16(s);
}

// ============ K3: fea2/q/ga via bf16 MMA (16 rows x 192 cols, cp.async staging) ==
__global__ void k_fea2q(const float* __restrict__ feb, const float* __restrict__ qb,
                        const float* __restrict__ gw,  const float* __restrict__ gb) {
    const int SA = 72;
    __shared__ __align__(16) __nv_bfloat16 As[16 * 72];
    __shared__ __align__(16) __nv_bfloat16 Bs[192 * 72];
    __shared__ float Fs[16 * 128];
    int tid = threadIdx.x, w = tid >> 5, lane = tid & 31;
    int r = lane >> 2, qp = lane & 3;
    int row0 = blockIdx.x * 16;
    // A: 16 rows x 8 chunks
    for (int t2 = tid; t2 < 128; t2 += 256) {
        int row = t2 >> 3, seg = t2 & 7;
        cp16(&As[row * SA + seg * 8], g_feabf + (size_t)(row0 + row) * 64 + seg * 8);
    }
    // B: 192 rows x 9 chunks (pad region copied too; never read by MMA)
    for (int t2 = tid; t2 < 1728; t2 += 256) {
        int n = t2 / 9, seg = t2 % 9;
        cp16(&Bs[n * SA + seg * 8], g_w72 + n * 72 + seg * 8);
    }
    CP_COMMIT();
    CP_WAIT0();
    __syncthreads();
    float c[3][4];
#pragma unroll
    for (int nt = 0; nt < 3; nt++)
#pragma unroll
        for (int i = 0; i < 4; i++) c[nt][i] = 0.f;
#pragma unroll
    for (int ks = 0; ks < 4; ks++) {
        int k0 = ks * 16 + 2 * qp;
        unsigned a[4], b[3][2];
        a[0] = *(unsigned*)&As[r * SA + k0];
        a[1] = *(unsigned*)&As[(r + 8) * SA + k0];
        a[2] = *(unsigned*)&As[r * SA + k0 + 8];
        a[3] = *(unsigned*)&As[(r + 8) * SA + k0 + 8];
#pragma unroll
        for (int nt = 0; nt < 3; nt++) {
            int n = w * 24 + nt * 8 + r;
            b[nt][0] = *(unsigned*)&Bs[n * SA + k0];
            b[nt][1] = *(unsigned*)&Bs[n * SA + k0 + 8];
        }
#pragma unroll
        for (int nt = 0; nt < 3; nt++) mma_bf16(c[nt], a, b[nt]);
    }
#pragma unroll
    for (int nt = 0; nt < 3; nt++) {
        int col = w * 24 + nt * 8 + 2 * qp;
        if (col < 128) {
            float b0 = __ldg(feb + col), b1 = __ldg(feb + col + 1);
            float v00 = c[nt][0] + b0, v01 = c[nt][1] + b1;
            float v10 = c[nt][2] + b0, v11 = c[nt][3] + b1;
            Fs[r * 128 + col] = v00; Fs[r * 128 + col + 1] = v01;
            Fs[(r + 8) * 128 + col] = v10; Fs[(r + 8) * 128 + col + 1] = v11;
            *(__nv_bfloat162*)&g_fea2bf[(size_t)(row0 + r) * 128 + col] = __floats2bfloat162_rn(v00, v01);
            *(__nv_bfloat162*)&g_fea2bf[(size_t)(row0 + r + 8) * 128 + col] = __floats2bfloat162_rn(v10, v11);
        } else {
            int qc = col - 128;
            float b0 = __ldg(qb + qc), b1 = __ldg(qb + qc + 1);
            *(float2*)&g_q[(size_t)(row0 + r) * 64 + qc] = make_float2(c[nt][0] + b0, c[nt][1] + b1);
            *(float2*)&g_q[(size_t)(row0 + r + 8) * 64 + qc] = make_float2(c[nt][2] + b0, c[nt][3] + b1);
        }
    }
    __syncthreads();
#pragma unroll
    for (int rr = 0; rr < 2; rr++) {
        int lrow = w * 2 + rr;
        float v[4];
#pragma unroll
        for (int i = 0; i < 4; i++) v[i] = Fs[lrow * 128 + lane + 32 * i];
#pragma unroll
        for (int g = 0; g < 8; g++) {
            float dot = 0.f;
#pragma unroll
            for (int i = 0; i < 4; i++) dot += v[i] * __ldg(gw + (lane + 32 * i) * 8 + g);
#pragma unroll
            for (int off = 16; off > 0; off >>= 1) dot += __shfl_xor_sync(0xffffffffu, dot, off);
            if (lane == 0) g_ga[(row0 + lrow) * 8 + g] = 1.f / (1.f + __expf(-(dot + __ldg(gb + g))));
        }
    }
}

// ============ K5: act = fea2 @ cw, cp.async double-buffered bf16 MMA =============
__global__ void k_cluster() {
    const int SA = 40;
    __shared__ __align__(16) __nv_bfloat16 As[2][128 * 40];
    __shared__ __align__(16) __nv_bfloat16 Bs[2][128 * 40];
    int bn = blockIdx.x, bm = blockIdx.y;
    int tid = threadIdx.x, w = tid >> 5, lane = tid & 31;
    int r = lane >> 2, qp = lane & 3;
    int wm = (w & 3) * 32, wn = (w >> 2) * 64;
    const __nv_bfloat16* a_base = g_fea2bf + (size_t)(bm * 128) * 128;
    const __nv_bfloat16* b_base = g_cwbf + (size_t)(bn * 128) * 128;

    auto issue = [&](int st, int kc) {
#pragma unroll
        for (int t = tid; t < 512; t += 256) {
            int row = t >> 2, seg = t & 3;
            cp16(&As[st][row * SA + seg * 8], a_base + row * 128 + kc * 32 + seg * 8);
        }
#pragma unroll
        for (int t = tid; t < 512; t += 256) {
            int row = t >> 2, seg = t & 3;
            cp16(&Bs[st][row * SA + seg * 8], b_base + row * 128 + kc * 32 + seg * 8);
        }
    };

    float c[2][8][4];
#pragma unroll
    for (int ms = 0; ms < 2; ms++)
#pragma unroll
        for (int ns = 0; ns < 8; ns++)
#pragma unroll
            for (int i = 0; i < 4; i++) c[ms][ns][i] = 0.f;

    issue(0, 0); CP_COMMIT();
#pragma unroll
    for (int kc = 0; kc < 4; kc++) {
        int cur = kc & 1;
        if (kc < 3) { issue(1 - cur, kc + 1); CP_COMMIT(); CP_WAIT1(); }
        else CP_WAIT0();
        __syncthreads();
#pragma unroll
        for (int ks = 0; ks < 2; ks++) {
            int k0 = ks * 16 + 2 * qp;
            unsigned a[2][4], b[8][2];
#pragma unroll
            for (int ms = 0; ms < 2; ms++) {
                int row = wm + ms * 16 + r;
                a[ms][0] = *(unsigned*)&As[cur][row * SA + k0];
                a[ms][1] = *(unsigned*)&As[cur][(row + 8) * SA + k0];
                a[ms][2] = *(unsigned*)&As[cur][row * SA + k0 + 8];
                a[ms][3] = *(unsigned*)&As[cur][(row + 8) * SA + k0 + 8];
            }
#pragma unroll
            for (int ns = 0; ns < 8; ns++) {
                int n = wn + ns * 8 + r;
                b[ns][0] = *(unsigned*)&Bs[cur][n * SA + k0];
                b[ns][1] = *(unsigned*)&Bs[cur][n * SA + k0 + 8];
            }
#pragma unroll
            for (int ms = 0; ms < 2; ms++)
#pragma unroll
                for (int ns = 0; ns < 8; ns++) mma_bf16(c[ms][ns], a[ms], b[ns]);
        }
        if (kc < 3) __syncthreads();
    }
#pragma unroll
    for (int ms = 0; ms < 2; ms++)
#pragma unroll
        for (int ns = 0; ns < 8; ns++) {
            int row = bm * 128 + wm + ms * 16 + r;
            int col = bn * 128 + wn + ns * 8 + 2 * qp;
            *(__nv_bfloat162*)(g_act + (size_t)row * 1024 + col) = __floats2bfloat162_rn(c[ms][ns][0], c[ms][ns][1]);
            *(__nv_bfloat162*)(g_act + (size_t)(row + 8) * 1024 + col) = __floats2bfloat162_rn(c[ms][ns][2], c[ms][ns][3]);
        }
#pragma unroll
    for (int ns = 0; ns < 8; ns++) {
        float s0 = 0.f, s1 = 0.f, q0 = 0.f, q1 = 0.f;
#pragma unroll
        for (int ms = 0; ms < 2; ms++) {
            s0 += c[ms][ns][0] + c[ms][ns][2];
            s1 += c[ms][ns][1] + c[ms][ns][3];
            q0 += c[ms][ns][0] * c[ms][ns][0] + c[ms][ns][2] * c[ms][ns][2];
            q1 += c[ms][ns][1] * c[ms][ns][1] + c[ms][ns][3] * c[ms][ns][3];
        }
#pragma unroll
        for (int off = 4; off < 32; off <<= 1) {
            s0 += __shfl_xor_sync(0xffffffffu, s0, off);
            s1 += __shfl_xor_sync(0xffffffffu, s1, off);
            q0 += __shfl_xor_sync(0xffffffffu, q0, off);
            q1 += __shfl_xor_sync(0xffffffffu, q1, off);
        }
        if (r == 0) {
            int col = bn * 128 + wn + ns * 8 + 2 * qp;
            atomicAdd(&g_csum[col], s0);
            atomicAdd(&g_csumsq[col], q0);
            atomicAdd(&g_csum[col + 1], s1);
            atomicAdd(&g_csumsq[col + 1], q1);
        }
    }
}

// ============ K8: BN-affine (fused) + softmax + ga -> cent (512 blocks) ==========
__global__ void k_smcent(const float* __restrict__ abg, const float* __restrict__ abb) {
    __shared__ float sc[2048];
    __shared__ float sA[1024], sB[1024];
    int tid = threadIdx.x;
    for (int i = tid; i < 2048; i += 256) sc[i] = 0.f;
    for (int i = tid; i < 1024; i += 256) {
        float m = g_csum[i] * (1.f / 8192.f);
        float var = g_csumsq[i] * (1.f / 8192.f) - m * m;
        float A = rsqrtf(var + 1e-5f) * __ldg(abg + i);
        sA[i] = A;
        sB[i] = __ldg(abb + i) - m * A;
    }
    __syncthreads();
    int blk = blockIdx.x;
    int b = blk >> 8, blkInB = blk & 255;
    int warp = tid >> 5, lane = tid & 31;
    int cols[4] = {2 * lane, 2 * lane + 1, 64 + 2 * lane, 64 + 2 * lane + 1};
    float acc[4][16];
#pragma unroll
    for (int i = 0; i < 4; i++)
#pragma unroll
        for (int f = 0; f < 16; f++) acc[i][f] = 0.f;
    int nbase = blkInB * 128 + warp * 16;
    for (int rr = 0; rr < 16; rr++) {
        int n = nbase + rr;
        int patch = n >> 3, grp = n & 7;
        const __nv_bfloat16* arow = g_act + (size_t)(b * 4096 + patch) * 1024 + grp * 128;
        float2 lo = __bfloat1622float2(*(const __nv_bfloat162*)(arow + 2 * lane));
        float2 hi = __bfloat1622float2(*(const __nv_bfloat162*)(arow + 64 + 2 * lane));
        float raw[4] = {lo.x, lo.y, hi.x, hi.y};
        float v[4];
#pragma unroll
        for (int i = 0; i < 4; i++)
            v[i] = raw[i] * sA[grp * 128 + cols[i]] + sB[grp * 128 + cols[i]];
        float m = fmaxf(fmaxf(v[0], v[1]), fmaxf(v[2], v[3]));
#pragma unroll
        for (int off = 16; off > 0; off >>= 1) m = fmaxf(m, __shfl_xor_sync(0xffffffffu, m, off));
        float p[4], ssum = 0.f;
#pragma unroll
        for (int i = 0; i < 4; i++) { p[i] = __expf(v[i] - m); ssum += p[i]; }
#pragma unroll
        for (int off = 16; off > 0; off >>= 1) ssum += __shfl_xor_sync(0xffffffffu, ssum, off);
        float scale = g_ga[b * 32768 + n] / ssum;
#pragma unroll
        for (int i = 0; i < 4; i++) p[i] *= scale;
        const __nv_bfloat16* f2 = g_fea2bf + (size_t)(b * 4096 + patch) * 128 + grp * 16;
        float fv = (lane < 16) ? __bfloat162float(f2[lane]) : 0.f;
#pragma unroll
        for (int f = 0; f < 16; f++) {
            float fvf = __shfl_sync(0xffffffffu, fv, f);
#pragma unroll
            for (int i = 0; i < 4; i++) acc[i][f] += p[i] * fvf;
        }
    }
#pragma unroll
    for (int i = 0; i < 4; i++)
#pragma unroll
        for (int f = 0; f < 16; f++) atomicAdd(&sc[cols[i] * 16 + f], acc[i][f]);
    __syncthreads();
    for (int i = tid; i < 2048; i += 256) atomicAdd(&g_cent[b * 2048 + i], sc[i]);
}

// ============ K10: fused proj + per-c BN + kv ====================================
__global__ void k_bnkv(const float* __restrict__ pjw, const float* __restrict__ pjb,
                       const float* __restrict__ pg, const float* __restrict__ pb,
                       const float* __restrict__ kvw, const float* __restrict__ kvb) {
    __shared__ float rs[128], rq[128], scent[128];
    int c = blockIdx.x, t = threadIdx.x;
    int b = t >> 6, f = t & 63;
    float val = __ldg(pjb + f);
    const float* cr = g_cent + b * 2048 + c * 16;
#pragma unroll
    for (int g = 0; g < 16; g++) val += cr[g] * __ldg(pjw + g * 64 + f);
    rs[t] = val; rq[t] = val * val;
    __syncthreads();
    for (int s = 64; s > 0; s >>= 1) {
        if (t < s) { rs[t] += rs[t + s]; rq[t] += rq[t + s]; }
        __syncthreads();
    }
    float mean = rs[0] * (1.f / 128.f);
    float var  = rq[0] * (1.f / 128.f) - mean * mean;
    float A = rsqrtf(var + 1e-5f) * __ldg(pg + c);
    float B = __ldg(pb + c) - mean * A;
    scent[t] = val * A + B;
    __syncthreads();
    float a0 = __ldg(kvb + t), a1 = a0;
    for (int ff = 0; ff < 64; ff++) {
        float w = __ldg(kvw + ff * 128 + t);
        a0 += scent[ff] * w;
        a1 += scent[64 + ff] * w;
    }
    if (t < 64) {
        g_kT[t * 128 + c] = a0;
        g_kT[(64 + t) * 128 + c] = a1;
    } else {
        g_v[c * 64 + t - 64] = a0;
        g_v[8192 + c * 64 + t - 64] = a1;
    }
}

// ============ K11: attention =====================================================
__global__ void k_attn() {
    int warp = threadIdx.x >> 5, lane = threadIdx.x & 31;
    int n = blockIdx.x * 8 + warp;
    int b = n >> 12, patch = n & 4095;
    const float* qr = g_q + n * 64;
    float q0 = qr[lane], q1 = qr[lane + 32];
    float s[4] = {0,0,0,0};
    const float* kTb = g_kT + b * 8192;
#pragma unroll 8
    for (int f = 0; f < 32; f++) {
        float qf = __shfl_sync(0xffffffffu, q0, f);
        const float* kr = kTb + f * 128;
#pragma unroll
        for (int i = 0; i < 4; i++) s[i] += qf * kr[lane + 32 * i];
    }
#pragma unroll 8
    for (int f = 0; f < 32; f++) {
        float qf = __shfl_sync(0xffffffffu, q1, f);
        const float* kr = kTb + (f + 32) * 128;
#pragma unroll
        for (int i = 0; i < 4; i++) s[i] += qf * kr[lane + 32 * i];
    }
#pragma unroll
    for (int i = 0; i < 4; i++) s[i] *= 0.125f;
    float m = fmaxf(fmaxf(s[0], s[1]), fmaxf(s[2], s[3]));
#pragma unroll
    for (int off = 16; off > 0; off >>= 1) m = fmaxf(m, __shfl_xor_sync(0xffffffffu, m, off));
    float p[4], sum = 0.f;
#pragma unroll
    for (int i = 0; i < 4; i++) { p[i] = __expf(s[i] - m); sum += p[i]; }
#pragma unroll
    for (int off = 16; off > 0; off >>= 1) sum += __shfl_xor_sync(0xffffffffu, sum, off);
    float inv = 1.f / sum;
#pragma unroll
    for (int i = 0; i < 4; i++) p[i] *= inv;
    float of0 = 0.f, of1 = 0.f;
    const float* vb = g_v + b * 8192;
#pragma unroll 16
    for (int c = 0; c < 128; c++) {
        float pc = __shfl_sync(0xffffffffu, p[c >> 5], c & 31);
        of0 += pc * vb[c * 64 + lane];
        of1 += pc * vb[c * 64 + lane + 32];
    }
    int bd = patch >> 8, bh = (patch >> 4) & 15, bw = patch & 15;
    int f = lane;
    int d = bd * 4 + (f >> 4), h = bh * 4 + ((f >> 2) & 3), w = bw * 4 + (f & 3);
    g_newo[b * VOXB + (d << 12) + (h << 6) + w] = of0;
    f = lane + 32;
    d = bd * 4 + (f >> 4); h = bh * 4 + ((f >> 2) & 3); w = bw * 4 + (f & 3);
    g_newo[b * VOXB + (d << 12) + (h << 6) + w] = of1;
}

// ============ K12: conv2 (R11 shape + cp.async weight staging) ===================
__global__ void __launch_bounds__(256, 4) k_conv2(
        const float* __restrict__ x, const float* __restrict__ upcb,
        float* __restrict__ out) {
    const int SA = 40;
    __shared__ float halo[3 * 4 * 66];
    __shared__ __align__(16) __nv_bfloat16 As[128 * 40];
    __shared__ __align__(16) __nv_bfloat16 Bs[96 * 40];
    int tid = threadIdx.x, w = tid >> 5, lane = tid & 31;
    int r = lane >> 2, qp = lane & 3;
    int blk = blockIdx.x;
    int ht = blk & 31, d = (blk >> 5) & 63, b = blk >> 11;
    int h0 = ht * 2;
    int v0 = ((b * 64 + d) * 64 + h0) * 64;
    // weights via cp.async (96 rows x 5 chunks = 480)
    for (int t2 = tid; t2 < 480; t2 += 256) {
        int c = t2 / 5, seg = t2 % 5;
        cp16(&Bs[c * SA + seg * 8], g_upc40 + c * 40 + seg * 8);
    }
    CP_COMMIT();
    const float* xb = x + (size_t)v0 * 96;
    for (int i = tid; i < 384; i += 256)
        asm volatile("prefetch.global.L2 [%0];" :: "l"(xb + i * 32));
    for (int i = tid; i < 792; i += 256) {
        int dd = i / 264, rem = i % 264, hh = rem / 66, ww = rem % 66;
        int gd = d - 1 + dd, gh = h0 - 1 + hh, gw = ww - 1;
        float val = 0.f;
        if ((unsigned)gd < 64u && (unsigned)gh < 64u && (unsigned)gw < 64u)
            val = g_newo[b * VOXB + (gd << 12) + (gh << 6) + gw];
        halo[i] = val;
    }
    CP_WAIT0();
    __syncthreads();
    for (int i = tid; i < 128 * 32; i += 256) {
        int vox = i >> 5, j = i & 31;
        float val = 0.f;
        if (j < 27) {
            int kd = j / 9, kh = (j % 9) / 3, kw = j % 3;
            val = halo[(kd * 4 + (vox >> 6) + kh) * 66 + (vox & 63) + kw];
        }
        As[vox * SA + j] = __float2bfloat16(val);
    }
    __syncthreads();
    int wm = (w & 3) * 32, wn = (w >> 2) * 48;
    float c[2][6][4];
#pragma unroll
    for (int ms = 0; ms < 2; ms++)
#pragma unroll
        for (int ns = 0; ns < 6; ns++)
#pragma unroll
            for (int i = 0; i < 4; i++) c[ms][ns][i] = 0.f;
#pragma unroll
    for (int ks = 0; ks < 2; ks++) {
        int k0 = ks * 16 + 2 * qp;
        unsigned a[2][4], bfr[6][2];
#pragma unroll
        for (int ms = 0; ms < 2; ms++) {
            int row = wm + ms * 16 + r;
            a[ms][0] = *(unsigned*)&As[row * SA + k0];
            a[ms][1] = *(unsigned*)&As[(row + 8) * SA + k0];
            a[ms][2] = *(unsigned*)&As[row * SA + k0 + 8];
            a[ms][3] = *(unsigned*)&As[(row + 8) * SA + k0 + 8];
        }
#pragma unroll
        for (int ns = 0; ns < 6; ns++) {
            int n = wn + ns * 8 + r;
            bfr[ns][0] = *(unsigned*)&Bs[n * SA + k0];
            bfr[ns][1] = *(unsigned*)&Bs[n * SA + k0 + 8];
        }
#pragma unroll
        for (int ms = 0; ms < 2; ms++)
#pragma unroll
            for (int ns = 0; ns < 6; ns++) mma_bf16(c[ms][ns], a[ms], bfr[ns]);
    }
#pragma unroll
    for (int ms = 0; ms < 2; ms++)
#pragma unroll
        for (int ns = 0; ns < 6; ns++) {
            int vl = wm + ms * 16 + r;
            int col = wn + ns * 8 + 2 * qp;
            float b0 = __ldg(upcb + col), b1 = __ldg(upcb + col + 1);
            size_t base0 = (size_t)(v0 + vl) * 96 + col;
            size_t base1 = (size_t)(v0 + vl + 8) * 96 + col;
            float2 x0 = *(const float2*)(x + base0);
            float2 x1 = *(const float2*)(x + base1);
            *(float2*)(out + base0) = make_float2(c[ms][ns][0] + x0.x + b0, c[ms][ns][1] + x0.y + b1);
            *(float2*)(out + base1) = make_float2(c[ms][ns][2] + x1.x + b0, c[ms][ns][3] + x1.y + b1);
        }
}

extern "C" void kernel_launch(void* const* d_in, const int* in_sizes, int n_in,
                              void* d_out, int out_size) {
    const float* x      = (const float*)d_in[0];
    const float* dwc_w  = (const float*)d_in[1];
    const float* dwc_b  = (const float*)d_in[2];
    const float* upc_w  = (const float*)d_in[3];
    const float* upc_b  = (const float*)d_in[4];
    const float* few    = (const float*)d_in[5];
    const float* feb    = (const float*)d_in[6];
    const float* gaw    = (const float*)d_in[7];
    const float* gab    = (const float*)d_in[8];
    const float* cw     = (const float*)d_in[9];
    const float* abg    = (const float*)d_in[10];
    const float* abb    = (const float*)d_in[11];
    const float* pjw    = (const float*)d_in[12];
    const float* pjb    = (const float*)d_in[13];
    const float* pbg    = (const float*)d_in[14];
    const float* pbb    = (const float*)d_in[15];
    const float* qw     = (const float*)d_in[16];
    const float* qb     = (const float*)d_in[17];
    const float* kvw    = (const float*)d_in[18];
    const float* kvb    = (const float*)d_in[19];
    float* out = (float*)d_out;

    k_prelude<<<135, 256>>>(cw, few, qw, dwc_w, upc_w);
    k_conv1A<<<4096, 256>>>(x);
    k_conv1B<<<2048, 256>>>(dwc_b);
    k_fea2q<<<512, 256>>>(feb, qb, gaw, gab);   // <- profiled slot (#4)
    k_cluster<<<dim3(8, 64), 256>>>();
    k_smcent<<<512, 256>>>(abg, abb);
    k_bnkv<<<128, 128>>>(pjw, pjb, pbg, pbb, kvw, kvb);
    k_attn<<<1024, 256>>>();
    k_conv2<<<4096, 256>>>(x, upc_b, out);
}

// round 17
// speedup vs baseline: 1.0645x; 1.0645x over previous
#include <cuda_runtime.h>
#include <cuda_bf16.h>

#define NVOX 524288
#define VOXB 262144

__device__ __nv_bfloat16 g_y[27 * NVOX];
__device__ __align__(16) __nv_bfloat16 g_feabf[8192 * 64];
__device__ __align__(16) __nv_bfloat16 g_w72[192 * 72];
__device__ __align__(16) __nv_bfloat16 g_fea2bf[8192 * 128];
__device__ __align__(16) __nv_bfloat16 g_cwbf[1024 * 128];
__device__ float g_q[8192 * 64];
__device__ float g_ga[65536];
__device__ __nv_bfloat16 g_act[8192 * 1024];
__device__ float g_csum[1024];
__device__ float g_csumsq[1024];
__device__ float g_cent[2 * 128 * 16];
__device__ float g_kT[2 * 64 * 128];
__device__ float g_v[2 * 128 * 64];
__device__ float g_newo[NVOX];

__device__ __forceinline__ void mma_bf16(float c[4], const unsigned a[4], const unsigned b[2]) {
    asm volatile(
        "mma.sync.aligned.m16n8k16.row.col.f32.bf16.bf16.f32 "
        "{%0,%1,%2,%3}, {%4,%5,%6,%7}, {%8,%9}, {%0,%1,%2,%3};"
        : "+f"(c[0]), "+f"(c[1]), "+f"(c[2]), "+f"(c[3])
        : "r"(a[0]), "r"(a[1]), "r"(a[2]), "r"(a[3]), "r"(b[0]), "r"(b[1]));
}

__device__ __forceinline__ unsigned pack_bf16(float lo, float hi) {
    __nv_bfloat162 h = __floats2bfloat162_rn(lo, hi);
    return *(unsigned*)&h;
}

__device__ __forceinline__ void cp16(void* dst, const void* src) {
    unsigned d = (unsigned)__cvta_generic_to_shared(dst);
    asm volatile("cp.async.ca.shared.global [%0], [%1], 16;" :: "r"(d), "l"(src));
}
#define CP_COMMIT() asm volatile("cp.async.commit_group;")
#define CP_WAIT1()  asm volatile("cp.async.wait_group 1;")
#define CP_WAIT0()  asm volatile("cp.async.wait_group 0;")

// ============ P: merged prelude ==================================================
__global__ void k_prelude(const float* __restrict__ cw, const float* __restrict__ few,
                          const float* __restrict__ qw) {
    if (blockIdx.x == 0) {
        int t = threadIdx.x;
        for (int i = t; i < 1024; i += 256) { g_csum[i] = 0.f; g_csumsq[i] = 0.f; }
        for (int i = t; i < 4096; i += 256) g_cent[i] = 0.f;
        return;
    }
    if (blockIdx.x >= 129) {
        int n0 = (blockIdx.x - 129) * 32;
        for (int i = threadIdx.x; i < 32 * 72; i += 256) {
            int n = n0 + i / 72, k = i % 72;
            float v = 0.f;
            if (k < 64) v = (n < 128) ? few[k * 128 + n] : qw[k * 64 + (n - 128)];
            g_w72[(size_t)n * 72 + (i % 72)] = __float2bfloat16(v);
        }
        return;
    }
    __shared__ float s[32][33];
    int bx = blockIdx.x - 1;
    int n0 = (bx & 31) * 32, k0 = (bx >> 5) * 32;
    int lane = threadIdx.x & 31, wr = threadIdx.x >> 5;
#pragma unroll
    for (int i = 0; i < 4; i++) {
        int k = k0 + wr + i * 8;
        s[wr + i * 8][lane] = cw[(size_t)k * 1024 + n0 + lane];
    }
    __syncthreads();
#pragma unroll
    for (int i = 0; i < 4; i++) {
        int n = n0 + wr + i * 8;
        g_cwbf[(size_t)n * 128 + k0 + lane] = __float2bfloat16(s[lane][wr + i * 8]);
    }
}

// ============ K1: conv1 stage A via bf16 MMA (R15 version) =======================
__global__ void k_conv1A(const float* __restrict__ x, const float* __restrict__ dwc_w) {
    const int SA = 104;
    __shared__ __nv_bfloat16 As[128 * 104];
    __shared__ __nv_bfloat16 Bs[32 * 104];
    int tid = threadIdx.x, w = tid >> 5, lane = tid & 31;
    int r = lane >> 2, qp = lane & 3;
    int v0 = blockIdx.x * 128;
#pragma unroll
    for (int it = 0; it < 12; it++) {
        int idx = it * 256 + tid;
        int row = idx / 24, p = idx % 24;
        float4 f = *(const float4*)(x + (size_t)(v0 + row) * 96 + 4 * p);
        uint2 u = make_uint2(pack_bf16(f.x, f.y), pack_bf16(f.z, f.w));
        *(uint2*)&As[row * SA + 4 * p] = u;
    }
    for (int i = tid; i < 32 * 96; i += 256) {
        int j = i / 96, c = i % 96;
        Bs[j * SA + c] = __float2bfloat16(j < 27 ? dwc_w[c * 27 + j] : 0.f);
    }
    __syncthreads();
    int wm = (w & 3) * 32, wn = (w >> 2) * 16;
    float c[2][2][4];
#pragma unroll
    for (int ms = 0; ms < 2; ms++)
#pragma unroll
        for (int ns = 0; ns < 2; ns++)
#pragma unroll
            for (int i = 0; i < 4; i++) c[ms][ns][i] = 0.f;
#pragma unroll
    for (int ks = 0; ks < 6; ks++) {
        int k0 = ks * 16 + 2 * qp;
        unsigned a[2][4], b[2][2];
#pragma unroll
        for (int ms = 0; ms < 2; ms++) {
            int row = wm + ms * 16 + r;
            a[ms][0] = *(unsigned*)&As[row * SA + k0];
            a[ms][1] = *(unsigned*)&As[(row + 8) * SA + k0];
            a[ms][2] = *(unsigned*)&As[row * SA + k0 + 8];
            a[ms][3] = *(unsigned*)&As[(row + 8) * SA + k0 + 8];
        }
#pragma unroll
        for (int ns = 0; ns < 2; ns++) {
            int n = wn + ns * 8 + r;
            b[ns][0] = *(unsigned*)&Bs[n * SA + k0];
            b[ns][1] = *(unsigned*)&Bs[n * SA + k0 + 8];
        }
#pragma unroll
        for (int ms = 0; ms < 2; ms++)
#pragma unroll
            for (int ns = 0; ns < 2; ns++) mma_bf16(c[ms][ns], a[ms], b[ns]);
    }
#pragma unroll
    for (int ms = 0; ms < 2; ms++)
#pragma unroll
        for (int ns = 0; ns < 2; ns++) {
            int v = v0 + wm + ms * 16 + r;
            int j0 = wn + ns * 8 + 2 * qp;
            if (j0 < 27) {
                g_y[j0 * NVOX + v] = __float2bfloat16(c[ms][ns][0]);
                g_y[j0 * NVOX + v + 8] = __float2bfloat16(c[ms][ns][2]);
            }
            if (j0 + 1 < 27) {
                g_y[(j0 + 1) * NVOX + v] = __float2bfloat16(c[ms][ns][1]);
                g_y[(j0 + 1) * NVOX + v + 8] = __float2bfloat16(c[ms][ns][3]);
            }
        }
}

// ============ K2: gather 27 shifted taps + bias -> feabf (b,4096,64) =============
__global__ void k_conv1B(const float* __restrict__ dwc_b) {
    int t = blockIdx.x * 256 + threadIdx.x;
    int b = t >> 18;
    int vox = t & (VOXB - 1);
    int d = vox >> 12, h = (vox >> 6) & 63, w = vox & 63;
    float s = dwc_b[0];
#pragma unroll
    for (int kd = 0; kd < 3; kd++)
#pragma unroll
        for (int kh = 0; kh < 3; kh++)
#pragma unroll
            for (int kw = 0; kw < 3; kw++) {
                int dd = d + kd - 1, hh = h + kh - 1, ww = w + kw - 1;
                if ((unsigned)dd < 64u && (unsigned)hh < 64u && (unsigned)ww < 64u)
                    s += __bfloat162float(g_y[(kd * 9 + kh * 3 + kw) * NVOX + b * VOXB + (dd << 12) + (hh << 6) + ww]);
            }
    int n = ((d >> 2) << 8) + ((h >> 2) << 4) + (w >> 2);
    int f = ((d & 3) << 4) + ((h & 3) << 2) + (w & 3);
    g_feabf[((b << 12) + n) * 64 + f] = __float2bfloat16(s);
}

// ============ K3: fea2/q/ga via bf16 MMA (cp.async staging — the one new piece) ==
__global__ void k_fea2q(const float* __restrict__ feb, const float* __restrict__ qb,
                        const float* __restrict__ gw,  const float* __restrict__ gb) {
    const int SA = 72;
    __shared__ __align__(16) __nv_bfloat16 As[16 * 72];
    __shared__ __align__(16) __nv_bfloat16 Bs[192 * 72];
    __shared__ float Fs[16 * 128];
    int tid = threadIdx.x, w = tid >> 5, lane = tid & 31;
    int r = lane >> 2, qp = lane & 3;
    int row0 = blockIdx.x * 16;
    for (int t2 = tid; t2 < 128; t2 += 256) {
        int row = t2 >> 3, seg = t2 & 7;
        cp16(&As[row * SA + seg * 8], g_feabf + (size_t)(row0 + row) * 64 + seg * 8);
    }
    for (int t2 = tid; t2 < 1728; t2 += 256) {
        int n = t2 / 9, seg = t2 % 9;
        cp16(&Bs[n * SA + seg * 8], g_w72 + (size_t)n * 72 + seg * 8);
    }
    CP_COMMIT();
    CP_WAIT0();
    __syncthreads();
    float c[3][4];
#pragma unroll
    for (int nt = 0; nt < 3; nt++)
#pragma unroll
        for (int i = 0; i < 4; i++) c[nt][i] = 0.f;
#pragma unroll
    for (int ks = 0; ks < 4; ks++) {
        int k0 = ks * 16 + 2 * qp;
        unsigned a[4], b[3][2];
        a[0] = *(unsigned*)&As[r * SA + k0];
        a[1] = *(unsigned*)&As[(r + 8) * SA + k0];
        a[2] = *(unsigned*)&As[r * SA + k0 + 8];
        a[3] = *(unsigned*)&As[(r + 8) * SA + k0 + 8];
#pragma unroll
        for (int nt = 0; nt < 3; nt++) {
            int n = w * 24 + nt * 8 + r;
            b[nt][0] = *(unsigned*)&Bs[n * SA + k0];
            b[nt][1] = *(unsigned*)&Bs[n * SA + k0 + 8];
        }
#pragma unroll
        for (int nt = 0; nt < 3; nt++) mma_bf16(c[nt], a, b[nt]);
    }
#pragma unroll
    for (int nt = 0; nt < 3; nt++) {
        int col = w * 24 + nt * 8 + 2 * qp;
        if (col < 128) {
            float b0 = __ldg(feb + col), b1 = __ldg(feb + col + 1);
            float v00 = c[nt][0] + b0, v01 = c[nt][1] + b1;
            float v10 = c[nt][2] + b0, v11 = c[nt][3] + b1;
            Fs[r * 128 + col] = v00; Fs[r * 128 + col + 1] = v01;
            Fs[(r + 8) * 128 + col] = v10; Fs[(r + 8) * 128 + col + 1] = v11;
            *(__nv_bfloat162*)&g_fea2bf[(size_t)(row0 + r) * 128 + col] = __floats2bfloat162_rn(v00, v01);
            *(__nv_bfloat162*)&g_fea2bf[(size_t)(row0 + r + 8) * 128 + col] = __floats2bfloat162_rn(v10, v11);
        } else {
            int qc = col - 128;
            float b0 = __ldg(qb + qc), b1 = __ldg(qb + qc + 1);
            *(float2*)&g_q[(size_t)(row0 + r) * 64 + qc] = make_float2(c[nt][0] + b0, c[nt][1] + b1);
            *(float2*)&g_q[(size_t)(row0 + r + 8) * 64 + qc] = make_float2(c[nt][2] + b0, c[nt][3] + b1);
        }
    }
    __syncthreads();
#pragma unroll
    for (int rr = 0; rr < 2; rr++) {
        int lrow = w * 2 + rr;
        float v[4];
#pragma unroll
        for (int i = 0; i < 4; i++) v[i] = Fs[lrow * 128 + lane + 32 * i];
#pragma unroll
        for (int g = 0; g < 8; g++) {
            float dot = 0.f;
#pragma unroll
            for (int i = 0; i < 4; i++) dot += v[i] * __ldg(gw + (lane + 32 * i) * 8 + g);
#pragma unroll
            for (int off = 16; off > 0; off >>= 1) dot += __shfl_xor_sync(0xffffffffu, dot, off);
            if (lane == 0) g_ga[(row0 + lrow) * 8 + g] = 1.f / (1.f + __expf(-(dot + __ldg(gb + g))));
        }
    }
}

// ============ K5: act = fea2 @ cw, cp.async double-buffered bf16 MMA =============
__global__ void k_cluster() {
    const int SA = 40;
    __shared__ __align__(16) __nv_bfloat16 As[2][128 * 40];
    __shared__ __align__(16) __nv_bfloat16 Bs[2][128 * 40];
    int bn = blockIdx.x, bm = blockIdx.y;
    int tid = threadIdx.x, w = tid >> 5, lane = tid & 31;
    int r = lane >> 2, qp = lane & 3;
    int wm = (w & 3) * 32, wn = (w >> 2) * 64;
    const __nv_bfloat16* a_base = g_fea2bf + (size_t)(bm * 128) * 128;
    const __nv_bfloat16* b_base = g_cwbf + (size_t)(bn * 128) * 128;

    auto issue = [&](int st, int kc) {
#pragma unroll
        for (int t = tid; t < 512; t += 256) {
            int row = t >> 2, seg = t & 3;
            cp16(&As[st][row * SA + seg * 8], a_base + row * 128 + kc * 32 + seg * 8);
        }
#pragma unroll
        for (int t = tid; t < 512; t += 256) {
            int row = t >> 2, seg = t & 3;
            cp16(&Bs[st][row * SA + seg * 8], b_base + row * 128 + kc * 32 + seg * 8);
        }
    };

    float c[2][8][4];
#pragma unroll
    for (int ms = 0; ms < 2; ms++)
#pragma unroll
        for (int ns = 0; ns < 8; ns++)
#pragma unroll
            for (int i = 0; i < 4; i++) c[ms][ns][i] = 0.f;

    issue(0, 0); CP_COMMIT();
#pragma unroll
    for (int kc = 0; kc < 4; kc++) {
        int cur = kc & 1;
        if (kc < 3) { issue(1 - cur, kc + 1); CP_COMMIT(); CP_WAIT1(); }
        else CP_WAIT0();
        __syncthreads();
#pragma unroll
        for (int ks = 0; ks < 2; ks++) {
            int k0 = ks * 16 + 2 * qp;
            unsigned a[2][4], b[8][2];
#pragma unroll
            for (int ms = 0; ms < 2; ms++) {
                int row = wm + ms * 16 + r;
                a[ms][0] = *(unsigned*)&As[cur][row * SA + k0];
                a[ms][1] = *(unsigned*)&As[cur][(row + 8) * SA + k0];
                a[ms][2] = *(unsigned*)&As[cur][row * SA + k0 + 8];
                a[ms][3] = *(unsigned*)&As[cur][(row + 8) * SA + k0 + 8];
            }
#pragma unroll
            for (int ns = 0; ns < 8; ns++) {
                int n = wn + ns * 8 + r;
                b[ns][0] = *(unsigned*)&Bs[cur][n * SA + k0];
                b[ns][1] = *(unsigned*)&Bs[cur][n * SA + k0 + 8];
            }
#pragma unroll
            for (int ms = 0; ms < 2; ms++)
#pragma unroll
                for (int ns = 0; ns < 8; ns++) mma_bf16(c[ms][ns], a[ms], b[ns]);
        }
        if (kc < 3) __syncthreads();
    }
#pragma unroll
    for (int ms = 0; ms < 2; ms++)
#pragma unroll
        for (int ns = 0; ns < 8; ns++) {
            int row = bm * 128 + wm + ms * 16 + r;
            int col = bn * 128 + wn + ns * 8 + 2 * qp;
            *(__nv_bfloat162*)(g_act + (size_t)row * 1024 + col) = __floats2bfloat162_rn(c[ms][ns][0], c[ms][ns][1]);
            *(__nv_bfloat162*)(g_act + (size_t)(row + 8) * 1024 + col) = __floats2bfloat162_rn(c[ms][ns][2], c[ms][ns][3]);
        }
#pragma unroll
    for (int ns = 0; ns < 8; ns++) {
        float s0 = 0.f, s1 = 0.f, q0 = 0.f, q1 = 0.f;
#pragma unroll
        for (int ms = 0; ms < 2; ms++) {
            s0 += c[ms][ns][0] + c[ms][ns][2];
            s1 += c[ms][ns][1] + c[ms][ns][3];
            q0 += c[ms][ns][0] * c[ms][ns][0] + c[ms][ns][2] * c[ms][ns][2];
            q1 += c[ms][ns][1] * c[ms][ns][1] + c[ms][ns][3] * c[ms][ns][3];
        }
#pragma unroll
        for (int off = 4; off < 32; off <<= 1) {
            s0 += __shfl_xor_sync(0xffffffffu, s0, off);
            s1 += __shfl_xor_sync(0xffffffffu, s1, off);
            q0 += __shfl_xor_sync(0xffffffffu, q0, off);
            q1 += __shfl_xor_sync(0xffffffffu, q1, off);
        }
        if (r == 0) {
            int col = bn * 128 + wn + ns * 8 + 2 * qp;
            atomicAdd(&g_csum[col], s0);
            atomicAdd(&g_csumsq[col], q0);
            atomicAdd(&g_csum[col + 1], s1);
            atomicAdd(&g_csumsq[col + 1], q1);
        }
    }
}

// ============ K8: BN-affine (fused) + softmax + ga -> cent (256 blocks, R15) =====
__global__ void k_smcent(const float* __restrict__ abg, const float* __restrict__ abb) {
    __shared__ float sc[2048];
    __shared__ float sA[1024], sB[1024];
    int tid = threadIdx.x;
    for (int i = tid; i < 2048; i += 256) sc[i] = 0.f;
    for (int i = tid; i < 1024; i += 256) {
        float m = g_csum[i] * (1.f / 8192.f);
        float var = g_csumsq[i] * (1.f / 8192.f) - m * m;
        float A = rsqrtf(var + 1e-5f) * __ldg(abg + i);
        sA[i] = A;
        sB[i] = __ldg(abb + i) - m * A;
    }
    __syncthreads();
    int blk = blockIdx.x;
    int b = blk >> 7, blkInB = blk & 127;
    int warp = tid >> 5, lane = tid & 31;
    int cols[4] = {2 * lane, 2 * lane + 1, 64 + 2 * lane, 64 + 2 * lane + 1};
    float acc[4][16];
#pragma unroll
    for (int i = 0; i < 4; i++)
#pragma unroll
        for (int f = 0; f < 16; f++) acc[i][f] = 0.f;
    int nbase = blkInB * 256 + warp * 32;
    for (int rr = 0; rr < 32; rr++) {
        int n = nbase + rr;
        int patch = n >> 3, grp = n & 7;
        const __nv_bfloat16* arow = g_act + (size_t)(b * 4096 + patch) * 1024 + grp * 128;
        float2 lo = __bfloat1622float2(*(const __nv_bfloat162*)(arow + 2 * lane));
        float2 hi = __bfloat1622float2(*(const __nv_bfloat162*)(arow + 64 + 2 * lane));
        float raw[4] = {lo.x, lo.y, hi.x, hi.y};
        float v[4];
#pragma unroll
        for (int i = 0; i < 4; i++)
            v[i] = raw[i] * sA[grp * 128 + cols[i]] + sB[grp * 128 + cols[i]];
        float m = fmaxf(fmaxf(v[0], v[1]), fmaxf(v[2], v[3]));
#pragma unroll
        for (int off = 16; off > 0; off >>= 1) m = fmaxf(m, __shfl_xor_sync(0xffffffffu, m, off));
        float p[4], ssum = 0.f;
#pragma unroll
        for (int i = 0; i < 4; i++) { p[i] = __expf(v[i] - m); ssum += p[i]; }
#pragma unroll
        for (int off = 16; off > 0; off >>= 1) ssum += __shfl_xor_sync(0xffffffffu, ssum, off);
        float scale = g_ga[b * 32768 + n] / ssum;
#pragma unroll
        for (int i = 0; i < 4; i++) p[i] *= scale;
        const __nv_bfloat16* f2 = g_fea2bf + (size_t)(b * 4096 + patch) * 128 + grp * 16;
        float fv = (lane < 16) ? __bfloat162float(f2[lane]) : 0.f;
#pragma unroll
        for (int f = 0; f < 16; f++) {
            float fvf = __shfl_sync(0xffffffffu, fv, f);
#pragma unroll
            for (int i = 0; i < 4; i++) acc[i][f] += p[i] * fvf;
        }
    }
#pragma unroll
    for (int i = 0; i < 4; i++)
#pragma unroll
        for (int f = 0; f < 16; f++) atomicAdd(&sc[cols[i] * 16 + f], acc[i][f]);
    __syncthreads();
    for (int i = tid; i < 2048; i += 256) atomicAdd(&g_cent[b * 2048 + i], sc[i]);
}

// ============ K10: fused proj + per-c BN + kv ====================================
__global__ void k_bnkv(const float* __restrict__ pjw, const float* __restrict__ pjb,
                       const float* __restrict__ pg, const float* __restrict__ pb,
                       const float* __restrict__ kvw, const float* __restrict__ kvb) {
    __shared__ float rs[128], rq[128], scent[128];
    int c = blockIdx.x, t = threadIdx.x;
    int b = t >> 6, f = t & 63;
    float val = __ldg(pjb + f);
    const float* cr = g_cent + b * 2048 + c * 16;
#pragma unroll
    for (int g = 0; g < 16; g++) val += cr[g] * __ldg(pjw + g * 64 + f);
    rs[t] = val; rq[t] = val * val;
    __syncthreads();
    for (int s = 64; s > 0; s >>= 1) {
        if (t < s) { rs[t] += rs[t + s]; rq[t] += rq[t + s]; }
        __syncthreads();
    }
    float mean = rs[0] * (1.f / 128.f);
    float var  = rq[0] * (1.f / 128.f) - mean * mean;
    float A = rsqrtf(var + 1e-5f) * __ldg(pg + c);
    float B = __ldg(pb + c) - mean * A;
    scent[t] = val * A + B;
    __syncthreads();
    float a0 = __ldg(kvb + t), a1 = a0;
    for (int ff = 0; ff < 64; ff++) {
        float w = __ldg(kvw + ff * 128 + t);
        a0 += scent[ff] * w;
        a1 += scent[64 + ff] * w;
    }
    if (t < 64) {
        g_kT[t * 128 + c] = a0;
        g_kT[(64 + t) * 128 + c] = a1;
    } else {
        g_v[c * 64 + t - 64] = a0;
        g_v[8192 + c * 64 + t - 64] = a1;
    }
}

// ============ K11: attention =====================================================
__global__ void k_attn() {
    int warp = threadIdx.x >> 5, lane = threadIdx.x & 31;
    int n = blockIdx.x * 8 + warp;
    int b = n >> 12, patch = n & 4095;
    const float* qr = g_q + n * 64;
    float q0 = qr[lane], q1 = qr[lane + 32];
    float s[4] = {0,0,0,0};
    const float* kTb = g_kT + b * 8192;
#pragma unroll 8
    for (int f = 0; f < 32; f++) {
        float qf = __shfl_sync(0xffffffffu, q0, f);
        const float* kr = kTb + f * 128;
#pragma unroll
        for (int i = 0; i < 4; i++) s[i] += qf * kr[lane + 32 * i];
    }
#pragma unroll 8
    for (int f = 0; f < 32; f++) {
        float qf = __shfl_sync(0xffffffffu, q1, f);
        const float* kr = kTb + (f + 32) * 128;
#pragma unroll
        for (int i = 0; i < 4; i++) s[i] += qf * kr[lane + 32 * i];
    }
#pragma unroll
    for (int i = 0; i < 4; i++) s[i] *= 0.125f;
    float m = fmaxf(fmaxf(s[0], s[1]), fmaxf(s[2], s[3]));
#pragma unroll
    for (int off = 16; off > 0; off >>= 1) m = fmaxf(m, __shfl_xor_sync(0xffffffffu, m, off));
    float p[4], sum = 0.f;
#pragma unroll
    for (int i = 0; i < 4; i++) { p[i] = __expf(s[i] - m); sum += p[i]; }
#pragma unroll
    for (int off = 16; off > 0; off >>= 1) sum += __shfl_xor_sync(0xffffffffu, sum, off);
    float inv = 1.f / sum;
#pragma unroll
    for (int i = 0; i < 4; i++) p[i] *= inv;
    float of0 = 0.f, of1 = 0.f;
    const float* vb = g_v + b * 8192;
#pragma unroll 16
    for (int c = 0; c < 128; c++) {
        float pc = __shfl_sync(0xffffffffu, p[c >> 5], c & 31);
        of0 += pc * vb[c * 64 + lane];
        of1 += pc * vb[c * 64 + lane + 32];
    }
    int bd = patch >> 8, bh = (patch >> 4) & 15, bw = patch & 15;
    int f = lane;
    int d = bd * 4 + (f >> 4), h = bh * 4 + ((f >> 2) & 3), w = bw * 4 + (f & 3);
    g_newo[b * VOXB + (d << 12) + (h << 6) + w] = of0;
    f = lane + 32;
    d = bd * 4 + (f >> 4); h = bh * 4 + ((f >> 2) & 3); w = bw * 4 + (f & 3);
    g_newo[b * VOXB + (d << 12) + (h << 6) + w] = of1;
}

// ============ K12: conv2 (R15/R11 version — verified best) =======================
__global__ void __launch_bounds__(256, 4) k_conv2(
        const float* __restrict__ x, const float* __restrict__ upcw,
        const float* __restrict__ upcb, float* __restrict__ out) {
    const int SA = 40;
    __shared__ float halo[3 * 4 * 66];
    __shared__ __nv_bfloat16 As[128 * 40];
    __shared__ __nv_bfloat16 Bs[96 * 40];
    int tid = threadIdx.x, w = tid >> 5, lane = tid & 31;
    int r = lane >> 2, qp = lane & 3;
    int blk = blockIdx.x;
    int ht = blk & 31, d = (blk >> 5) & 63, b = blk >> 11;
    int h0 = ht * 2;
    int v0 = ((b * 64 + d) * 64 + h0) * 64;
    const float* xb = x + (size_t)v0 * 96;
    for (int i = tid; i < 384; i += 256)
        asm volatile("prefetch.global.L2 [%0];" :: "l"(xb + i * 32));
    for (int i = tid; i < 792; i += 256) {
        int dd = i / 264, rem = i % 264, hh = rem / 66, ww = rem % 66;
        int gd = d - 1 + dd, gh = h0 - 1 + hh, gw = ww - 1;
        float val = 0.f;
        if ((unsigned)gd < 64u && (unsigned)gh < 64u && (unsigned)gw < 64u)
            val = g_newo[b * VOXB + (gd << 12) + (gh << 6) + gw];
        halo[i] = val;
    }
    for (int i = tid; i < 96 * 32; i += 256) {
        int c = i >> 5, j = i & 31;
        Bs[c * SA + j] = __float2bfloat16(j < 27 ? upcw[c * 27 + j] : 0.f);
    }
    __syncthreads();
    for (int i = tid; i < 128 * 32; i += 256) {
        int vox = i >> 5, j = i & 31;
        float val = 0.f;
        if (j < 27) {
            int kd = j / 9, kh = (j % 9) / 3, kw = j % 3;
            val = halo[(kd * 4 + (vox >> 6) + kh) * 66 + (vox & 63) + kw];
        }
        As[vox * SA + j] = __float2bfloat16(val);
    }
    __syncthreads();
    int wm = (w & 3) * 32, wn = (w >> 2) * 48;
    float c[2][6][4];
#pragma unroll
    for (int ms = 0; ms < 2; ms++)
#pragma unroll
        for (int ns = 0; ns < 6; ns++)
#pragma unroll
            for (int i = 0; i < 4; i++) c[ms][ns][i] = 0.f;
#pragma unroll
    for (int ks = 0; ks < 2; ks++) {
        int k0 = ks * 16 + 2 * qp;
        unsigned a[2][4], bfr[6][2];
#pragma unroll
        for (int ms = 0; ms < 2; ms++) {
            int row = wm + ms * 16 + r;
            a[ms][0] = *(unsigned*)&As[row * SA + k0];
            a[ms][1] = *(unsigned*)&As[(row + 8) * SA + k0];
            a[ms][2] = *(unsigned*)&As[row * SA + k0 + 8];
            a[ms][3] = *(unsigned*)&As[(row + 8) * SA + k0 + 8];
        }
#pragma unroll
        for (int ns = 0; ns < 6; ns++) {
            int n = wn + ns * 8 + r;
            bfr[ns][0] = *(unsigned*)&Bs[n * SA + k0];
            bfr[ns][1] = *(unsigned*)&Bs[n * SA + k0 + 8];
        }
#pragma unroll
        for (int ms = 0; ms < 2; ms++)
#pragma unroll
            for (int ns = 0; ns < 6; ns++) mma_bf16(c[ms][ns], a[ms], bfr[ns]);
    }
#pragma unroll
    for (int ms = 0; ms < 2; ms++)
#pragma unroll
        for (int ns = 0; ns < 6; ns++) {
            int vl = wm + ms * 16 + r;
            int col = wn + ns * 8 + 2 * qp;
            float b0 = __ldg(upcb + col), b1 = __ldg(upcb + col + 1);
            size_t base0 = (size_t)(v0 + vl) * 96 + col;
            size_t base1 = (size_t)(v0 + vl + 8) * 96 + col;
            float2 x0 = *(const float2*)(x + base0);
            float2 x1 = *(const float2*)(x + base1);
            *(float2*)(out + base0) = make_float2(c[ms][ns][0] + x0.x + b0, c[ms][ns][1] + x0.y + b1);
            *(float2*)(out + base1) = make_float2(c[ms][ns][2] + x1.x + b0, c[ms][ns][3] + x1.y + b1);
        }
}

extern "C" void kernel_launch(void* const* d_in, const int* in_sizes, int n_in,
                              void* d_out, int out_size) {
    const float* x      = (const float*)d_in[0];
    const float* dwc_w  = (const float*)d_in[1];
    const float* dwc_b  = (const float*)d_in[2];
    const float* upc_w  = (const float*)d_in[3];
    const float* upc_b  = (const float*)d_in[4];
    const float* few    = (const float*)d_in[5];
    const float* feb    = (const float*)d_in[6];
    const float* gaw    = (const float*)d_in[7];
    const float* gab    = (const float*)d_in[8];
    const float* cw     = (const float*)d_in[9];
    const float* abg    = (const float*)d_in[10];
    const float* abb    = (const float*)d_in[11];
    const float* pjw    = (const float*)d_in[12];
    const float* pjb    = (const float*)d_in[13];
    const float* pbg    = (const float*)d_in[14];
    const float* pbb    = (const float*)d_in[15];
    const float* qw     = (const float*)d_in[16];
    const float* qb     = (const float*)d_in[17];
    const float* kvw    = (const float*)d_in[18];
    const float* kvb    = (const float*)d_in[19];
    float* out = (float*)d_out;

    k_prelude<<<135, 256>>>(cw, few, qw);
    k_conv1A<<<4096, 256>>>(x, dwc_w);
    k_conv1B<<<2048, 256>>>(dwc_b);
    k_fea2q<<<512, 256>>>(feb, qb, gaw, gab);   // <- profiled slot (#4)
    k_cluster<<<dim3(8, 64), 256>>>();
    k_smcent<<<256, 256>>>(abg, abb);
    k_bnkv<<<128, 128>>>(pjw, pjb, pbg, pbb, kvw, kvb);
    k_attn<<<1024, 256>>>();
    k_conv2<<<4096, 256>>>(x, upc_w, upc_b, out);
}